// round 1
// baseline (speedup 1.0000x reference)
#include <cuda_runtime.h>
#include <math.h>

#define N_NODES 10000
#define N_EDGES 160000
#define F_DIM 4
#define T_DIM 12
#define C_DIM 512
#define HID_DIM 256
#define OUT_DIM 12
#define FT (F_DIM * T_DIM)

// ---------------- scratch (no allocations allowed: __device__ globals) ----------------
__device__ float g_deg[N_NODES];
__device__ float g_dinv[N_NODES];
__device__ float g_agg[(size_t)N_NODES * FT];
__device__ float g_U[3 * F_DIM * C_DIM];
__device__ float g_beff[3 * C_DIM];
__device__ float g_probs[T_DIM];
__device__ float g_H[2][(size_t)N_NODES * C_DIM];
__device__ float g_z[(size_t)N_NODES * C_DIM];
__device__ float g_Hr[(size_t)N_NODES * C_DIM];
__device__ float g_Hacc[(size_t)N_NODES * C_DIM];
__device__ float g_h1[(size_t)N_NODES * HID_DIM];

// ---------------- small setup kernels ----------------
__global__ void init_state(float* H0, float* Hacc, float* deg) {
    int idx = blockIdx.x * blockDim.x + threadIdx.x;
    if (idx < N_NODES * C_DIM) { H0[idx] = 0.f; Hacc[idx] = 0.f; }
    if (idx < N_NODES) deg[idx] = 1.f;   // self-loop weight 1
}

__global__ void deg_scatter(const int* __restrict__ ei, const float* __restrict__ ea,
                            float* __restrict__ deg) {
    int e = blockIdx.x * blockDim.x + threadIdx.x;
    if (e >= N_EDGES) return;
    atomicAdd(&deg[ei[N_EDGES + e]], ea[e]);   // dst = row 1
}

__global__ void compute_dinv(const float* __restrict__ deg, float* __restrict__ dinv) {
    int i = blockIdx.x * blockDim.x + threadIdx.x;
    if (i >= N_NODES) return;
    dinv[i] = rsqrtf(fmaxf(deg[i], 1e-12f));
}

// agg[i,:] = dinv[i]^2 * x[i,:]   (self-loop term)
__global__ void agg_init(const float* __restrict__ x, const float* __restrict__ dinv,
                         float* __restrict__ agg) {
    int idx = blockIdx.x * blockDim.x + threadIdx.x;
    if (idx >= N_NODES * FT) return;
    int i = idx / FT;
    float d = dinv[i];
    agg[idx] = d * d * x[idx];
}

// agg[dst,:] += dinv[src]*w*dinv[dst] * x[src,:]   over all edges, all 48 feats
__global__ void agg_scatter(const float* __restrict__ x, const int* __restrict__ ei,
                            const float* __restrict__ ea, const float* __restrict__ dinv,
                            float* __restrict__ agg) {
    long long idx = (long long)blockIdx.x * blockDim.x + threadIdx.x;
    if (idx >= (long long)N_EDGES * FT) return;
    int e = (int)(idx / FT);
    int k = (int)(idx % FT);
    int s = ei[e];
    int d = ei[N_EDGES + e];
    float coef = dinv[s] * ea[e] * dinv[d];
    atomicAdd(&agg[(size_t)d * FT + k], coef * x[(size_t)s * FT + k]);
}

__global__ void softmax12(const float* __restrict__ att, float* __restrict__ probs) {
    if (threadIdx.x == 0) {
        float m = -1e30f;
        for (int i = 0; i < T_DIM; i++) m = fmaxf(m, att[i]);
        float e[T_DIM]; float s = 0.f;
        for (int i = 0; i < T_DIM; i++) { e[i] = expf(att[i] - m); s += e[i]; }
        float inv = 1.f / s;
        for (int i = 0; i < T_DIM; i++) probs[i] = e[i] * inv;
    }
}

// U[g][f][c] = sum_k Wg[f][k] * Wl[k][c]   (fold GCN weight through top half of Wl)
__global__ void compute_U(const float* Wzg, const float* Wrg, const float* Whg,
                          const float* Wzl, const float* Wrl, const float* Whl,
                          float* U) {
    int idx = blockIdx.x * blockDim.x + threadIdx.x;
    if (idx >= 3 * F_DIM * C_DIM) return;
    int g = idx / (F_DIM * C_DIM);
    int rem = idx % (F_DIM * C_DIM);
    int f = rem / C_DIM;
    int c = rem % C_DIM;
    const float* Wg = (g == 0) ? Wzg : (g == 1) ? Wrg : Whg;
    const float* Wl = (g == 0) ? Wzl : (g == 1) ? Wrl : Whl;
    float s = 0.f;
    for (int k = 0; k < C_DIM; k++) s += Wg[f * C_DIM + k] * Wl[(size_t)k * C_DIM + c];
    U[idx] = s;
}

// beff[g][c] = sum_k bg[k] * Wl[k][c] + bl[c]
__global__ void compute_beff(const float* bzg, const float* brg, const float* bhg,
                             const float* Wzl, const float* Wrl, const float* Whl,
                             const float* bzl, const float* brl, const float* bhl,
                             float* beff) {
    int idx = blockIdx.x * blockDim.x + threadIdx.x;
    if (idx >= 3 * C_DIM) return;
    int g = idx / C_DIM;
    int c = idx % C_DIM;
    const float* bg = (g == 0) ? bzg : (g == 1) ? brg : bhg;
    const float* Wl = (g == 0) ? Wzl : (g == 1) ? Wrl : Whl;
    const float* bl = (g == 0) ? bzl : (g == 1) ? brl : bhl;
    float s = bl[c];
    for (int k = 0; k < C_DIM; k++) s += bg[k] * Wl[(size_t)k * C_DIM + c];
    beff[idx] = s;
}

// ---------------- fused SGEMM (K=512 fixed): C = A@B (+rank-4 agg term) + bias, fused epilogue ----------------
// mode 0: z = sigmoid(pre)                     -> out0 = z
// mode 1: Hr = Hin * sigmoid(pre)              -> out0 = Hr
// mode 2: ht = tanh(pre); Hn = z*Hin+(1-z)*ht  -> out0 = Hnew, Hacc += probs[t]*Hn
// mode 3: head1: out0 = relu(pre) (beff=b1, no rank4, A relu'd on load)
#define BM 128
#define BN 128
#define BKK 8

__global__ __launch_bounds__(256) void gemm_fused(
    const float* __restrict__ A, const float* __restrict__ B,
    int M, int Nc, int mode, int t, int reluA,
    const float* __restrict__ agg, const float* __restrict__ U,
    const float* __restrict__ beff,
    const float* __restrict__ Hin, const float* __restrict__ Z,
    float* __restrict__ out0, float* __restrict__ Hacc,
    const float* __restrict__ probs)
{
    const int K = 512;
    __shared__ float As[BKK][BM];
    __shared__ float Bs[BKK][BN];

    int tid = threadIdx.x;
    int row0 = blockIdx.y * BM;
    int col0 = blockIdx.x * BN;
    int ty = tid >> 4;      // 0..15
    int tx = tid & 15;      // 0..15

    float acc[8][8];
#pragma unroll
    for (int i = 0; i < 8; i++)
#pragma unroll
        for (int j = 0; j < 8; j++) acc[i][j] = 0.f;

    int aRow = tid >> 1;            // 0..127
    int aCol = (tid & 1) << 2;      // 0 or 4
    int bRow = tid >> 5;            // 0..7
    int bCol = (tid & 31) << 2;     // 0..124

    int ar = row0 + aRow;
    bool aValid = (ar < M);
    const float4* Arow = (const float4*)(A + (size_t)ar * K);

    for (int k0 = 0; k0 < K; k0 += BKK) {
        float4 av = make_float4(0.f, 0.f, 0.f, 0.f);
        if (aValid) av = Arow[(k0 + aCol) >> 2];
        if (reluA) {
            av.x = fmaxf(av.x, 0.f); av.y = fmaxf(av.y, 0.f);
            av.z = fmaxf(av.z, 0.f); av.w = fmaxf(av.w, 0.f);
        }
        As[aCol + 0][aRow] = av.x;
        As[aCol + 1][aRow] = av.y;
        As[aCol + 2][aRow] = av.z;
        As[aCol + 3][aRow] = av.w;

        float4 bv = *(const float4*)(B + (size_t)(k0 + bRow) * Nc + col0 + bCol);
        *(float4*)&Bs[bRow][bCol] = bv;
        __syncthreads();

#pragma unroll
        for (int kk = 0; kk < BKK; kk++) {
            float ra[8], rb[8];
            *(float4*)&ra[0] = *(const float4*)&As[kk][ty * 8];
            *(float4*)&ra[4] = *(const float4*)&As[kk][ty * 8 + 4];
            *(float4*)&rb[0] = *(const float4*)&Bs[kk][tx * 8];
            *(float4*)&rb[4] = *(const float4*)&Bs[kk][tx * 8 + 4];
#pragma unroll
            for (int i = 0; i < 8; i++)
#pragma unroll
                for (int j = 0; j < 8; j++)
                    acc[i][j] = fmaf(ra[i], rb[j], acc[i][j]);
        }
        __syncthreads();
    }

    float p = (mode == 2) ? probs[t] : 0.f;

#pragma unroll
    for (int i = 0; i < 8; i++) {
        int r = row0 + ty * 8 + i;
        if (r >= M) continue;
        float a0 = 0.f, a1 = 0.f, a2 = 0.f, a3 = 0.f;
        if (mode != 3) {
            const float* ag = agg + (size_t)r * FT + t;
            a0 = ag[0]; a1 = ag[T_DIM]; a2 = ag[2 * T_DIM]; a3 = ag[3 * T_DIM];
        }
#pragma unroll
        for (int j = 0; j < 8; j++) {
            int c = col0 + tx * 8 + j;
            float v = acc[i][j] + beff[c];
            if (mode != 3)
                v += a0 * U[c] + a1 * U[C_DIM + c] + a2 * U[2 * C_DIM + c] + a3 * U[3 * C_DIM + c];
            size_t o = (size_t)r * Nc + c;
            if (mode == 0) {
                out0[o] = 1.f / (1.f + expf(-v));
            } else if (mode == 1) {
                out0[o] = Hin[o] * (1.f / (1.f + expf(-v)));
            } else if (mode == 2) {
                float ht = tanhf(v);
                float zz = Z[o];
                float hn = zz * Hin[o] + (1.f - zz) * ht;
                out0[o] = hn;
                Hacc[o] += p * hn;
            } else {
                out0[o] = fmaxf(v, 0.f);
            }
        }
    }
}

// out[i,j] = h1[i,:] @ W2[:,j] + b2[j]
__global__ void head2(const float* __restrict__ h1, const float* __restrict__ W2,
                      const float* __restrict__ b2, float* __restrict__ out) {
    int idx = blockIdx.x * blockDim.x + threadIdx.x;
    if (idx >= N_NODES * OUT_DIM) return;
    int i = idx / OUT_DIM;
    int j = idx % OUT_DIM;
    float s = b2[j];
    const float* hr = h1 + (size_t)i * HID_DIM;
    for (int k = 0; k < HID_DIM; k++) s += hr[k] * W2[k * OUT_DIM + j];
    out[idx] = s;
}

__global__ void copy_hidden(const float* __restrict__ Hacc, float* __restrict__ out) {
    int idx = blockIdx.x * blockDim.x + threadIdx.x;
    if (idx >= N_NODES * C_DIM) return;
    out[idx] = Hacc[idx];
}

// ---------------- host launcher ----------------
extern "C" void kernel_launch(void* const* d_in, const int* in_sizes, int n_in,
                              void* d_out, int out_size) {
    const float* x   = (const float*)d_in[0];
    const int*   ei  = (const int*)d_in[1];
    const float* ea  = (const float*)d_in[2];
    const float* att = (const float*)d_in[3];
    const float* Wg[3] = {(const float*)d_in[4],  (const float*)d_in[8],  (const float*)d_in[12]};
    const float* bg[3] = {(const float*)d_in[5],  (const float*)d_in[9],  (const float*)d_in[13]};
    const float* Wl[3] = {(const float*)d_in[6],  (const float*)d_in[10], (const float*)d_in[14]};
    const float* bl[3] = {(const float*)d_in[7],  (const float*)d_in[11], (const float*)d_in[15]};
    const float* W1 = (const float*)d_in[16];
    const float* b1 = (const float*)d_in[17];
    const float* W2 = (const float*)d_in[18];
    const float* b2 = (const float*)d_in[19];
    float* out = (float*)d_out;

    float *deg, *dinv, *agg, *U, *beff, *probs, *Hbase, *zb, *Hr, *Hacc, *h1;
    cudaGetSymbolAddress((void**)&deg,   g_deg);
    cudaGetSymbolAddress((void**)&dinv,  g_dinv);
    cudaGetSymbolAddress((void**)&agg,   g_agg);
    cudaGetSymbolAddress((void**)&U,     g_U);
    cudaGetSymbolAddress((void**)&beff,  g_beff);
    cudaGetSymbolAddress((void**)&probs, g_probs);
    cudaGetSymbolAddress((void**)&Hbase, g_H);
    cudaGetSymbolAddress((void**)&zb,    g_z);
    cudaGetSymbolAddress((void**)&Hr,    g_Hr);
    cudaGetSymbolAddress((void**)&Hacc,  g_Hacc);
    cudaGetSymbolAddress((void**)&h1,    g_h1);
    float* H[2] = {Hbase, Hbase + (size_t)N_NODES * C_DIM};

    // setup
    init_state<<<(N_NODES * C_DIM + 255) / 256, 256>>>(H[0], Hacc, deg);
    deg_scatter<<<(N_EDGES + 255) / 256, 256>>>(ei, ea, deg);
    compute_dinv<<<(N_NODES + 255) / 256, 256>>>(deg, dinv);
    agg_init<<<(N_NODES * FT + 255) / 256, 256>>>(x, dinv, agg);
    {
        long long tot = (long long)N_EDGES * FT;
        agg_scatter<<<(unsigned)((tot + 255) / 256), 256>>>(x, ei, ea, dinv, agg);
    }
    softmax12<<<1, 32>>>(att, probs);
    compute_U<<<(3 * F_DIM * C_DIM + 255) / 256, 256>>>(Wg[0], Wg[1], Wg[2], Wl[0], Wl[1], Wl[2], U);
    compute_beff<<<(3 * C_DIM + 255) / 256, 256>>>(bg[0], bg[1], bg[2], Wl[0], Wl[1], Wl[2],
                                                   bl[0], bl[1], bl[2], beff);

    dim3 blk(256);
    dim3 grid512(C_DIM / BN, (N_NODES + BM - 1) / BM);
    const size_t VOFF = (size_t)C_DIM * C_DIM;  // bottom half of W*_l: rows 512..1023
    int hin = 0;
    for (int t = 0; t < T_DIM; t++) {
        // z gate
        gemm_fused<<<grid512, blk>>>(H[hin], Wl[0] + VOFF, N_NODES, C_DIM, 0, t, 0,
                                     agg, U + 0 * F_DIM * C_DIM, beff + 0 * C_DIM,
                                     nullptr, nullptr, zb, nullptr, nullptr);
        // r gate -> Hr = H * r
        gemm_fused<<<grid512, blk>>>(H[hin], Wl[1] + VOFF, N_NODES, C_DIM, 1, t, 0,
                                     agg, U + 1 * F_DIM * C_DIM, beff + 1 * C_DIM,
                                     H[hin], nullptr, Hr, nullptr, nullptr);
        // h gate -> Hnew, Hacc += p*Hn
        gemm_fused<<<grid512, blk>>>(Hr, Wl[2] + VOFF, N_NODES, C_DIM, 2, t, 0,
                                     agg, U + 2 * F_DIM * C_DIM, beff + 2 * C_DIM,
                                     H[hin], zb, H[1 - hin], Hacc, probs);
        hin ^= 1;
    }

    // head: h1 = relu(relu(Hacc) @ W1 + b1)
    dim3 gridH(HID_DIM / BN, (N_NODES + BM - 1) / BM);
    gemm_fused<<<gridH, blk>>>(Hacc, W1, N_NODES, HID_DIM, 3, 0, 1,
                               nullptr, nullptr, b1, nullptr, nullptr, h1, nullptr, nullptr);
    // out h = h1 @ W2 + b2   (first 120000 floats)
    head2<<<(N_NODES * OUT_DIM + 255) / 256, 256>>>(h1, W2, b2, out);
    // out_hidden = H_accum    (next 5120000 floats)
    copy_hidden<<<(N_NODES * C_DIM + 255) / 256, 256>>>(Hacc, out + (size_t)N_NODES * OUT_DIM);
}

// round 3
// speedup vs baseline: 1.3893x; 1.3893x over previous
#include <cuda_runtime.h>
#include <cstdint>
#include <math.h>

#define N_NODES 10000
#define N_EDGES 160000
#define F_DIM 4
#define T_DIM 12
#define C_DIM 512
#define HID_DIM 256
#define OUT_DIM 12
#define FT (F_DIM * T_DIM)

// ---------------- scratch (__device__ globals; no allocations allowed) ----------------
__device__ float g_deg[N_NODES];
__device__ float g_dinv[N_NODES];
__device__ float g_agg[(size_t)N_NODES * FT];
__device__ float g_U[3 * F_DIM * C_DIM];          // per-gate [4][512]
__device__ float g_beff[3 * C_DIM];
__device__ float g_Uzr[F_DIM * 2 * C_DIM];        // [4][1024] z|r concat
__device__ float g_beffzr[2 * C_DIM];
__device__ float g_probs[T_DIM];
__device__ float g_H[2][(size_t)N_NODES * C_DIM];
__device__ float g_z[(size_t)N_NODES * C_DIM];
__device__ float g_Hr[(size_t)N_NODES * C_DIM];
__device__ float g_Hacc[(size_t)N_NODES * C_DIM];
__device__ float g_h1[(size_t)N_NODES * HID_DIM];
// transposed weights, [n][k] row-major, k stride 512:
//  [0 .. 1024*512)            : Btzr  (z cols 0..511, r cols 512..1023)
//  [1024*512 .. +512*512)     : Bth
//  [.. +256*512)              : Bt1 (W1 transposed)
#define BT_ZR_OFF 0
#define BT_H_OFF  (1024 * 512)
#define BT_1_OFF  (1024 * 512 + 512 * 512)
__device__ float g_Bt[(1024 + 512 + 256) * 512];

// ---------------- small setup kernels ----------------
__global__ void init_state(float* H0, float* Hacc, float* deg) {
    int idx = blockIdx.x * blockDim.x + threadIdx.x;
    if (idx < N_NODES * C_DIM) { H0[idx] = 0.f; Hacc[idx] = 0.f; }
    if (idx < N_NODES) deg[idx] = 1.f;
}
__global__ void deg_scatter(const int* __restrict__ ei, const float* __restrict__ ea,
                            float* __restrict__ deg) {
    int e = blockIdx.x * blockDim.x + threadIdx.x;
    if (e >= N_EDGES) return;
    atomicAdd(&deg[ei[N_EDGES + e]], ea[e]);
}
__global__ void compute_dinv(const float* __restrict__ deg, float* __restrict__ dinv) {
    int i = blockIdx.x * blockDim.x + threadIdx.x;
    if (i >= N_NODES) return;
    dinv[i] = rsqrtf(fmaxf(deg[i], 1e-12f));
}
__global__ void agg_init(const float* __restrict__ x, const float* __restrict__ dinv,
                         float* __restrict__ agg) {
    int idx = blockIdx.x * blockDim.x + threadIdx.x;
    if (idx >= N_NODES * FT) return;
    int i = idx / FT;
    float d = dinv[i];
    agg[idx] = d * d * x[idx];
}
__global__ void agg_scatter(const float* __restrict__ x, const int* __restrict__ ei,
                            const float* __restrict__ ea, const float* __restrict__ dinv,
                            float* __restrict__ agg) {
    long long idx = (long long)blockIdx.x * blockDim.x + threadIdx.x;
    if (idx >= (long long)N_EDGES * FT) return;
    int e = (int)(idx / FT);
    int k = (int)(idx % FT);
    int s = ei[e];
    int d = ei[N_EDGES + e];
    float coef = dinv[s] * ea[e] * dinv[d];
    atomicAdd(&agg[(size_t)d * FT + k], coef * x[(size_t)s * FT + k]);
}
__global__ void softmax12(const float* __restrict__ att, float* __restrict__ probs) {
    if (threadIdx.x == 0) {
        float m = -1e30f;
        for (int i = 0; i < T_DIM; i++) m = fmaxf(m, att[i]);
        float e[T_DIM]; float s = 0.f;
        for (int i = 0; i < T_DIM; i++) { e[i] = expf(att[i] - m); s += e[i]; }
        float inv = 1.f / s;
        for (int i = 0; i < T_DIM; i++) probs[i] = e[i] * inv;
    }
}
__global__ void compute_U(const float* Wzg, const float* Wrg, const float* Whg,
                          const float* Wzl, const float* Wrl, const float* Whl,
                          float* U) {
    int idx = blockIdx.x * blockDim.x + threadIdx.x;
    if (idx >= 3 * F_DIM * C_DIM) return;
    int g = idx / (F_DIM * C_DIM);
    int rem = idx % (F_DIM * C_DIM);
    int f = rem / C_DIM;
    int c = rem % C_DIM;
    const float* Wg = (g == 0) ? Wzg : (g == 1) ? Wrg : Whg;
    const float* Wl = (g == 0) ? Wzl : (g == 1) ? Wrl : Whl;
    float s = 0.f;
    for (int k = 0; k < C_DIM; k++) s += Wg[f * C_DIM + k] * Wl[(size_t)k * C_DIM + c];
    U[idx] = s;
}
__global__ void compute_beff(const float* bzg, const float* brg, const float* bhg,
                             const float* Wzl, const float* Wrl, const float* Whl,
                             const float* bzl, const float* brl, const float* bhl,
                             float* beff) {
    int idx = blockIdx.x * blockDim.x + threadIdx.x;
    if (idx >= 3 * C_DIM) return;
    int g = idx / C_DIM;
    int c = idx % C_DIM;
    const float* bg = (g == 0) ? bzg : (g == 1) ? brg : bhg;
    const float* Wl = (g == 0) ? Wzl : (g == 1) ? Wrl : Whl;
    const float* bl = (g == 0) ? bzl : (g == 1) ? brl : bhl;
    float s = bl[c];
    for (int k = 0; k < C_DIM; k++) s += bg[k] * Wl[(size_t)k * C_DIM + c];
    beff[idx] = s;
}
// pack z|r concatenated U/beff tables
__global__ void pack_zr(const float* __restrict__ U, const float* __restrict__ beff,
                        float* __restrict__ Uzr, float* __restrict__ beffzr) {
    int idx = blockIdx.x * blockDim.x + threadIdx.x;
    if (idx < F_DIM * 1024) {
        int f = idx >> 10;
        int c = idx & 1023;
        int gt = (c >> 9);            // 0 = z, 1 = r
        Uzr[idx] = U[gt * (F_DIM * C_DIM) + f * C_DIM + (c & 511)];
    }
    if (idx < 1024) {
        int gt = idx >> 9;
        beffzr[idx] = beff[gt * C_DIM + (idx & 511)];
    }
}
// build transposed weight blocks: Bt[n][k]
__global__ void transpose_B(const float* Wzl, const float* Wrl, const float* Whl,
                            const float* W1, float* __restrict__ Bt) {
    int idx = blockIdx.x * blockDim.x + threadIdx.x;
    const int ZR = 1024 * 512, HH = 512 * 512, W1N = 256 * 512;
    if (idx < ZR) {
        int n = idx >> 9, k = idx & 511;
        float v = (n < 512) ? Wzl[(size_t)(C_DIM + k) * C_DIM + n]
                            : Wrl[(size_t)(C_DIM + k) * C_DIM + (n - 512)];
        Bt[BT_ZR_OFF + idx] = v;
    } else if (idx < ZR + HH) {
        int r = idx - ZR;
        int n = r >> 9, k = r & 511;
        Bt[BT_H_OFF + r] = Whl[(size_t)(C_DIM + k) * C_DIM + n];
    } else if (idx < ZR + HH + W1N) {
        int r = idx - ZR - HH;
        int n = r >> 9, k = r & 511;
        Bt[BT_1_OFF + r] = W1[(size_t)k * HID_DIM + n];
    }
}

// ---------------- 3xTF32 mma.sync GEMM with fused GRU epilogue ----------------
// C[M, Nc] = A[M,512] @ Bt^T   (Bt stored [Nc][512])
// mode 0 (zr): c<512 -> zb=sigmoid(v);  c>=512 -> Hr = Hin*sigmoid(v)
// mode 2 (h):  ht=tanh(v); Hn=z*Hin+(1-z)*ht -> out0=Hn; Hacc += p*Hn
// mode 3 (head): out0 = relu(v)  (A relu'd on load, no rank-4 term)
#define BMT 128
#define BNT 128
#define BKT 32
#define SPAD 36

__device__ __forceinline__ void split_tf32(float x, uint32_t& hi, uint32_t& lo) {
    asm("cvt.rna.tf32.f32 %0, %1;" : "=r"(hi) : "f"(x));
    float hif = __uint_as_float(hi);
    float lof = x - hif;
    asm("cvt.rna.tf32.f32 %0, %1;" : "=r"(lo) : "f"(lof));
}
__device__ __forceinline__ void mma_tf32(float* c, const uint32_t* a, const uint32_t* b) {
    asm volatile(
        "mma.sync.aligned.m16n8k8.row.col.f32.tf32.tf32.f32 "
        "{%0,%1,%2,%3}, {%4,%5,%6,%7}, {%8,%9}, {%0,%1,%2,%3};"
        : "+f"(c[0]), "+f"(c[1]), "+f"(c[2]), "+f"(c[3])
        : "r"(a[0]), "r"(a[1]), "r"(a[2]), "r"(a[3]), "r"(b[0]), "r"(b[1]));
}

__global__ __launch_bounds__(256) void gemm_tf32(
    const float* __restrict__ A, const float* __restrict__ Bt,
    int M, int Nc, int mode, int t, int reluA,
    const float* __restrict__ agg, const float* __restrict__ U, int ustride,
    const float* __restrict__ beff,
    const float* __restrict__ Hin, const float* __restrict__ Z,
    float* __restrict__ out0, float* __restrict__ out1,
    float* __restrict__ Hacc, const float* __restrict__ probs)
{
    __shared__ float As[BMT][SPAD];
    __shared__ float Bs[BNT][SPAD];
    __shared__ float aggS[BMT][F_DIM];

    const int tid = threadIdx.x;
    const int wid = tid >> 5;
    const int lane = tid & 31;
    const int g8 = lane >> 2;       // 0..7
    const int tig = lane & 3;       // 0..3
    const int wm = wid >> 2;        // 0..1 -> m offset *64
    const int wn = wid & 3;         // 0..3 -> n offset *32
    const int row0 = blockIdx.y * BMT;
    const int col0 = blockIdx.x * BNT;

    // preload agg rows for the epilogue (rank-4 correction)
    if (mode != 3) {
        for (int i = tid; i < BMT * F_DIM; i += 256) {
            int r = i >> 2, f = i & 3;
            aggS[r][f] = (row0 + r < M) ? agg[(size_t)(row0 + r) * FT + f * T_DIM + t] : 0.f;
        }
    }

    float acc[4][4][4];
#pragma unroll
    for (int a = 0; a < 4; a++)
#pragma unroll
        for (int b = 0; b < 4; b++)
#pragma unroll
            for (int c = 0; c < 4; c++) acc[a][b][c] = 0.f;

    for (int kc = 0; kc < 16; kc++) {
        const int k0 = kc * BKT;
        // load A tile [128 x 32]
#pragma unroll
        for (int it = 0; it < 4; it++) {
            int idx = it * 256 + tid;    // 0..1023
            int r = idx >> 3;
            int c4 = idx & 7;
            float4 v = make_float4(0.f, 0.f, 0.f, 0.f);
            if (row0 + r < M) {
                v = *(const float4*)(A + (size_t)(row0 + r) * 512 + k0 + c4 * 4);
                if (reluA) {
                    v.x = fmaxf(v.x, 0.f); v.y = fmaxf(v.y, 0.f);
                    v.z = fmaxf(v.z, 0.f); v.w = fmaxf(v.w, 0.f);
                }
            }
            As[r][c4 * 4 + 0] = v.x; As[r][c4 * 4 + 1] = v.y;
            As[r][c4 * 4 + 2] = v.z; As[r][c4 * 4 + 3] = v.w;
        }
        // load B tile [128 x 32] (Bt is [Nc][512] row-major)
#pragma unroll
        for (int it = 0; it < 4; it++) {
            int idx = it * 256 + tid;
            int n = idx >> 3;
            int c4 = idx & 7;
            float4 v = *(const float4*)(Bt + (size_t)(col0 + n) * 512 + k0 + c4 * 4);
            Bs[n][c4 * 4 + 0] = v.x; Bs[n][c4 * 4 + 1] = v.y;
            Bs[n][c4 * 4 + 2] = v.z; Bs[n][c4 * 4 + 3] = v.w;
        }
        __syncthreads();

#pragma unroll
        for (int kk = 0; kk < BKT; kk += 8) {
            uint32_t ah[4][4], al[4][4];
#pragma unroll
            for (int mt = 0; mt < 4; mt++) {
                int r = wm * 64 + mt * 16 + g8;
                split_tf32(As[r][kk + tig],         ah[mt][0], al[mt][0]);
                split_tf32(As[r + 8][kk + tig],     ah[mt][1], al[mt][1]);
                split_tf32(As[r][kk + tig + 4],     ah[mt][2], al[mt][2]);
                split_tf32(As[r + 8][kk + tig + 4], ah[mt][3], al[mt][3]);
            }
            uint32_t bh[4][2], bl[4][2];
#pragma unroll
            for (int nt = 0; nt < 4; nt++) {
                int n = wn * 32 + nt * 8 + g8;
                split_tf32(Bs[n][kk + tig],     bh[nt][0], bl[nt][0]);
                split_tf32(Bs[n][kk + tig + 4], bh[nt][1], bl[nt][1]);
            }
#pragma unroll
            for (int mt = 0; mt < 4; mt++)
#pragma unroll
                for (int nt = 0; nt < 4; nt++) {
                    mma_tf32(acc[mt][nt], ah[mt], bh[nt]);
                    mma_tf32(acc[mt][nt], ah[mt], bl[nt]);
                    mma_tf32(acc[mt][nt], al[mt], bh[nt]);
                }
        }
        __syncthreads();
    }

    // ---- fused epilogue ----
    const float p = (mode == 2) ? probs[t] : 0.f;
#pragma unroll
    for (int mt = 0; mt < 4; mt++) {
#pragma unroll
        for (int i = 0; i < 2; i++) {
            int rl = wm * 64 + mt * 16 + g8 + i * 8;
            int gr = row0 + rl;
            if (gr >= M) continue;
            float a0 = 0.f, a1 = 0.f, a2 = 0.f, a3 = 0.f;
            if (mode != 3) {
                a0 = aggS[rl][0]; a1 = aggS[rl][1];
                a2 = aggS[rl][2]; a3 = aggS[rl][3];
            }
#pragma unroll
            for (int nt = 0; nt < 4; nt++) {
#pragma unroll
                for (int jj = 0; jj < 2; jj++) {
                    int cg = col0 + wn * 32 + nt * 8 + tig * 2 + jj;
                    float v = acc[mt][nt][i * 2 + jj] + beff[cg];
                    if (mode != 3)
                        v += a0 * U[cg] + a1 * U[ustride + cg]
                           + a2 * U[2 * ustride + cg] + a3 * U[3 * ustride + cg];
                    if (mode == 0) {
                        float s = 1.f / (1.f + expf(-v));
                        if (cg < 512) {
                            out0[(size_t)gr * C_DIM + cg] = s;
                        } else {
                            size_t o = (size_t)gr * C_DIM + (cg - 512);
                            out1[o] = Hin[o] * s;
                        }
                    } else if (mode == 2) {
                        size_t o = (size_t)gr * C_DIM + cg;
                        float ht = tanhf(v);
                        float zz = Z[o];
                        float hn = zz * Hin[o] + (1.f - zz) * ht;
                        out0[o] = hn;
                        Hacc[o] += p * hn;
                    } else {
                        out0[(size_t)gr * HID_DIM + cg] = fmaxf(v, 0.f);
                    }
                }
            }
        }
    }
}

// out[i,j] = h1[i,:] @ W2[:,j] + b2[j]
__global__ void head2(const float* __restrict__ h1, const float* __restrict__ W2,
                      const float* __restrict__ b2, float* __restrict__ out) {
    int idx = blockIdx.x * blockDim.x + threadIdx.x;
    if (idx >= N_NODES * OUT_DIM) return;
    int i = idx / OUT_DIM;
    int j = idx % OUT_DIM;
    float s = b2[j];
    const float* hr = h1 + (size_t)i * HID_DIM;
    for (int k = 0; k < HID_DIM; k++) s += hr[k] * W2[k * OUT_DIM + j];
    out[idx] = s;
}
__global__ void copy_hidden(const float* __restrict__ Hacc, float* __restrict__ out) {
    int idx = blockIdx.x * blockDim.x + threadIdx.x;
    if (idx >= N_NODES * C_DIM) return;
    out[idx] = Hacc[idx];
}

// ---------------- host launcher ----------------
extern "C" void kernel_launch(void* const* d_in, const int* in_sizes, int n_in,
                              void* d_out, int out_size) {
    const float* x   = (const float*)d_in[0];
    const int*   ei  = (const int*)d_in[1];
    const float* ea  = (const float*)d_in[2];
    const float* att = (const float*)d_in[3];
    const float* Wg[3] = {(const float*)d_in[4],  (const float*)d_in[8],  (const float*)d_in[12]};
    const float* bg[3] = {(const float*)d_in[5],  (const float*)d_in[9],  (const float*)d_in[13]};
    const float* Wl[3] = {(const float*)d_in[6],  (const float*)d_in[10], (const float*)d_in[14]};
    const float* bl[3] = {(const float*)d_in[7],  (const float*)d_in[11], (const float*)d_in[15]};
    const float* W1 = (const float*)d_in[16];
    const float* b1 = (const float*)d_in[17];
    const float* W2 = (const float*)d_in[18];
    const float* b2 = (const float*)d_in[19];
    float* out = (float*)d_out;

    float *deg, *dinv, *agg, *U, *beff, *Uzr, *beffzr, *probs, *Hbase, *zb, *Hr, *Hacc, *h1, *Bt;
    cudaGetSymbolAddress((void**)&deg,    g_deg);
    cudaGetSymbolAddress((void**)&dinv,   g_dinv);
    cudaGetSymbolAddress((void**)&agg,    g_agg);
    cudaGetSymbolAddress((void**)&U,      g_U);
    cudaGetSymbolAddress((void**)&beff,   g_beff);
    cudaGetSymbolAddress((void**)&Uzr,    g_Uzr);
    cudaGetSymbolAddress((void**)&beffzr, g_beffzr);
    cudaGetSymbolAddress((void**)&probs,  g_probs);
    cudaGetSymbolAddress((void**)&Hbase,  g_H);
    cudaGetSymbolAddress((void**)&zb,     g_z);
    cudaGetSymbolAddress((void**)&Hr,     g_Hr);
    cudaGetSymbolAddress((void**)&Hacc,   g_Hacc);
    cudaGetSymbolAddress((void**)&h1,     g_h1);
    cudaGetSymbolAddress((void**)&Bt,     g_Bt);
    float* H[2] = {Hbase, Hbase + (size_t)N_NODES * C_DIM};

    // setup
    init_state<<<(N_NODES * C_DIM + 255) / 256, 256>>>(H[0], Hacc, deg);
    deg_scatter<<<(N_EDGES + 255) / 256, 256>>>(ei, ea, deg);
    compute_dinv<<<(N_NODES + 255) / 256, 256>>>(deg, dinv);
    agg_init<<<(N_NODES * FT + 255) / 256, 256>>>(x, dinv, agg);
    {
        long long tot = (long long)N_EDGES * FT;
        agg_scatter<<<(unsigned)((tot + 255) / 256), 256>>>(x, ei, ea, dinv, agg);
    }
    softmax12<<<1, 32>>>(att, probs);
    compute_U<<<(3 * F_DIM * C_DIM + 255) / 256, 256>>>(Wg[0], Wg[1], Wg[2], Wl[0], Wl[1], Wl[2], U);
    compute_beff<<<(3 * C_DIM + 255) / 256, 256>>>(bg[0], bg[1], bg[2], Wl[0], Wl[1], Wl[2],
                                                   bl[0], bl[1], bl[2], beff);
    pack_zr<<<(F_DIM * 1024 + 255) / 256, 256>>>(U, beff, Uzr, beffzr);
    {
        int tot = (1024 + 512 + 256) * 512;
        transpose_B<<<(tot + 255) / 256, 256>>>(Wl[0], Wl[1], Wl[2], W1, Bt);
    }

    dim3 blk(256);
    dim3 gridZR(1024 / BNT, (N_NODES + BMT - 1) / BMT);   // (8, 79)
    dim3 gridH(512 / BNT, (N_NODES + BMT - 1) / BMT);     // (4, 79)
    int hin = 0;
    for (int t = 0; t < T_DIM; t++) {
        // fused z+r gates: z -> zb, Hr = H*r
        gemm_tf32<<<gridZR, blk>>>(H[hin], Bt + BT_ZR_OFF, N_NODES, 1024, 0, t, 0,
                                   agg, Uzr, 1024, beffzr,
                                   H[hin], nullptr, zb, Hr, nullptr, probs);
        // h gate: Hnew = z*H + (1-z)*tanh(...); Hacc += p*Hnew
        gemm_tf32<<<gridH, blk>>>(Hr, Bt + BT_H_OFF, N_NODES, 512, 2, t, 0,
                                  agg, U + 2 * F_DIM * C_DIM, 512, beff + 2 * C_DIM,
                                  H[hin], zb, H[1 - hin], nullptr, Hacc, probs);
        hin ^= 1;
    }

    // head: h1 = relu(relu(Hacc) @ W1 + b1)
    dim3 gridHead(HID_DIM / BNT, (N_NODES + BMT - 1) / BMT);   // (2, 79)
    gemm_tf32<<<gridHead, blk>>>(Hacc, Bt + BT_1_OFF, N_NODES, HID_DIM, 3, 0, 1,
                                 nullptr, nullptr, 0, b1,
                                 nullptr, nullptr, h1, nullptr, nullptr, probs);
    head2<<<(N_NODES * OUT_DIM + 255) / 256, 256>>>(h1, W2, b2, out);
    copy_hidden<<<(N_NODES * C_DIM + 255) / 256, 256>>>(Hacc, out + (size_t)N_NODES * OUT_DIM);
}